// round 2
// baseline (speedup 1.0000x reference)
#include <cuda_runtime.h>
#include <cuda_bf16.h>
#include <math.h>

#define B_  2
#define S_  2048
#define D_  1024
#define H_  16
#define DK_ 64
#define M_  (B_*S_)   // 4096

// ---- scratch (static device globals; no allocation allowed) ----
__device__ float g_Q[(size_t)M_*D_];
__device__ float g_K[(size_t)M_*D_];
__device__ float g_V[(size_t)M_*D_];
__device__ float g_HO[(size_t)M_*D_];
__device__ float g_P[(size_t)B_*H_*S_*S_];   // 134,217,728 floats = 512 MB

// ============================================================
// Unified batched NT SGEMM: C[m,n] = alpha * sum_k A[m,k]*B[n,k]
// Tile 128x128, BK=16, 256 threads, 8x8 per thread.
// z batch decoded as (zb, zh) = (z/HB, z%HB); per-z offsets via strides.
// Grid: (N/128, M/128, nz). All dims assumed multiples of tile sizes.
// ============================================================
__global__ __launch_bounds__(256) void sgemm_nt_bat(
    const float* __restrict__ A, int lda, long sAb, long sAh,
    const float* __restrict__ B, int ldb, long sBb, long sBh,
    float*       __restrict__ C, int ldc, long sCb, long sCh,
    int K, float alpha, int HB)
{
    int z  = blockIdx.z;
    int zb = z / HB, zh = z % HB;
    A += (size_t)zb * sAb + (size_t)zh * sAh;
    B += (size_t)zb * sBb + (size_t)zh * sBh;
    C += (size_t)zb * sCb + (size_t)zh * sCh;

    __shared__ float As[16][128];
    __shared__ float Bs[16][128];

    const int bm = blockIdx.y * 128;
    const int bn = blockIdx.x * 128;
    const int tid = threadIdx.x;
    const int tx = tid % 16, ty = tid / 16;

    const int lr  = tid / 4;   // 0..63  (row within half-tile)
    const int lc4 = tid % 4;   // 0..3   (float4 column -> k offset lc4*4)

    float acc[8][8];
    #pragma unroll
    for (int i = 0; i < 8; i++)
        #pragma unroll
        for (int j = 0; j < 8; j++) acc[i][j] = 0.f;

    for (int k0 = 0; k0 < K; k0 += 16) {
        #pragma unroll
        for (int h = 0; h < 2; h++) {
            int row = lr + h * 64;
            float4 va = *(const float4*)(A + (size_t)(bm + row) * lda + k0 + lc4 * 4);
            As[lc4*4+0][row] = va.x; As[lc4*4+1][row] = va.y;
            As[lc4*4+2][row] = va.z; As[lc4*4+3][row] = va.w;
            float4 vb = *(const float4*)(B + (size_t)(bn + row) * ldb + k0 + lc4 * 4);
            Bs[lc4*4+0][row] = vb.x; Bs[lc4*4+1][row] = vb.y;
            Bs[lc4*4+2][row] = vb.z; Bs[lc4*4+3][row] = vb.w;
        }
        __syncthreads();

        #pragma unroll
        for (int kk = 0; kk < 16; kk++) {
            float a[8], b[8];
            #pragma unroll
            for (int i = 0; i < 8; i++) a[i] = As[kk][ty*8 + i];
            #pragma unroll
            for (int j = 0; j < 8; j++) b[j] = Bs[kk][tx*8 + j];
            #pragma unroll
            for (int i = 0; i < 8; i++)
                #pragma unroll
                for (int j = 0; j < 8; j++) acc[i][j] += a[i] * b[j];
        }
        __syncthreads();
    }

    #pragma unroll
    for (int i = 0; i < 8; i++) {
        int row = bm + ty*8 + i;
        #pragma unroll
        for (int j = 0; j < 8; j++) {
            C[(size_t)row * ldc + bn + tx*8 + j] = alpha * acc[i][j];
        }
    }
}

// ============================================================
// Fused softmax over last dim + mean over heads.
// One block per (b, s) query row; loops over the 16 heads.
// Row length S_=2048, 256 threads, 8 elements/thread (2 float4).
// Writes normalized probs back into g_P and the head-mean into W.
// ============================================================
__global__ __launch_bounds__(256) void softmax_mean(float* __restrict__ P,
                                                    float* __restrict__ W)
{
    const int b = blockIdx.x >> 11;          // / 2048
    const int s = blockIdx.x & (S_ - 1);
    const int tid = threadIdx.x;
    const int lane = tid & 31, wid = tid >> 5;

    __shared__ float red[8];

    float acc[8];
    #pragma unroll
    for (int i = 0; i < 8; i++) acc[i] = 0.f;

    const int c0 = tid * 4;          // first float4 column
    const int c1 = 1024 + tid * 4;   // second float4 column

    for (int h = 0; h < H_; h++) {
        float* row = P + ((size_t)(b * H_ + h) * S_ + s) * S_;
        float v[8];
        float4 f0 = *(const float4*)(row + c0);
        float4 f1 = *(const float4*)(row + c1);
        v[0]=f0.x; v[1]=f0.y; v[2]=f0.z; v[3]=f0.w;
        v[4]=f1.x; v[5]=f1.y; v[6]=f1.z; v[7]=f1.w;

        // --- row max ---
        float m = v[0];
        #pragma unroll
        for (int i = 1; i < 8; i++) m = fmaxf(m, v[i]);
        #pragma unroll
        for (int o = 16; o > 0; o >>= 1) m = fmaxf(m, __shfl_xor_sync(0xffffffff, m, o));
        if (lane == 0) red[wid] = m;
        __syncthreads();
        if (wid == 0) {
            float t = red[lane & 7];
            #pragma unroll
            for (int o = 4; o > 0; o >>= 1) t = fmaxf(t, __shfl_xor_sync(0xffffffff, t, o));
            if (lane == 0) red[0] = t;
        }
        __syncthreads();
        m = red[0];
        __syncthreads();

        // --- exp + sum ---
        float sloc = 0.f;
        #pragma unroll
        for (int i = 0; i < 8; i++) { v[i] = __expf(v[i] - m); sloc += v[i]; }
        #pragma unroll
        for (int o = 16; o > 0; o >>= 1) sloc += __shfl_xor_sync(0xffffffff, sloc, o);
        if (lane == 0) red[wid] = sloc;
        __syncthreads();
        if (wid == 0) {
            float t = red[lane & 7];
            #pragma unroll
            for (int o = 4; o > 0; o >>= 1) t += __shfl_xor_sync(0xffffffff, t, o);
            if (lane == 0) red[0] = t;
        }
        __syncthreads();
        float inv = 1.0f / red[0];
        __syncthreads();

        // --- normalize, write back, accumulate mean ---
        #pragma unroll
        for (int i = 0; i < 8; i++) { v[i] *= inv; acc[i] += v[i] * (1.0f / H_); }
        float4 o0 = make_float4(v[0], v[1], v[2], v[3]);
        float4 o1 = make_float4(v[4], v[5], v[6], v[7]);
        *(float4*)(row + c0) = o0;
        *(float4*)(row + c1) = o1;
    }

    float* wrow = W + ((size_t)b * S_ + s) * S_;
    *(float4*)(wrow + c0) = make_float4(acc[0], acc[1], acc[2], acc[3]);
    *(float4*)(wrow + c1) = make_float4(acc[4], acc[5], acc[6], acc[7]);
}

// ============================================================
// attn @ V (NN GEMM): per (b,h): O[s, d] = sum_k P[s,k] * V[k, d], d in [0,64)
// Tile 128x64, BK=32, 256 threads, 8x4 per thread.
// Grid: (S/128, 1, B*H)
// ============================================================
__global__ __launch_bounds__(256) void av_nn(const float* __restrict__ P,
                                             const float* __restrict__ V,
                                             float* __restrict__ O)
{
    const int z = blockIdx.z;
    const int b = z / H_, h = z % H_;
    const float* Pz = P + (size_t)z * S_ * S_;
    const float* Vz = V + (size_t)b * S_ * D_ + h * DK_;
    float*       Oz = O + (size_t)b * S_ * D_ + h * DK_;

    const int bm = blockIdx.x * 128;
    const int tid = threadIdx.x;
    const int tx = tid % 16, ty = tid / 16;

    __shared__ float Ps[32][128];
    __shared__ float Vs[32][64];

    const int prow = tid / 8;    // 0..31
    const int pc4  = tid % 8;    // 0..7  -> k col pc4*4
    const int vrow = tid / 16;   // 0..15
    const int vc4  = tid % 16;   // 0..15 -> d col vc4*4

    float acc[8][4];
    #pragma unroll
    for (int i = 0; i < 8; i++)
        #pragma unroll
        for (int j = 0; j < 4; j++) acc[i][j] = 0.f;

    for (int k0 = 0; k0 < S_; k0 += 32) {
        #pragma unroll
        for (int p = 0; p < 4; p++) {
            int row = prow + p * 32;
            float4 v = *(const float4*)(Pz + (size_t)(bm + row) * S_ + k0 + pc4 * 4);
            Ps[pc4*4+0][row] = v.x; Ps[pc4*4+1][row] = v.y;
            Ps[pc4*4+2][row] = v.z; Ps[pc4*4+3][row] = v.w;
        }
        #pragma unroll
        for (int p = 0; p < 2; p++) {
            int kr = vrow + p * 16;
            *(float4*)(&Vs[kr][vc4*4]) =
                *(const float4*)(Vz + (size_t)(k0 + kr) * D_ + vc4 * 4);
        }
        __syncthreads();

        #pragma unroll
        for (int kk = 0; kk < 32; kk++) {
            float a[8], bb[4];
            #pragma unroll
            for (int i = 0; i < 8; i++) a[i] = Ps[kk][ty*8 + i];
            #pragma unroll
            for (int j = 0; j < 4; j++) bb[j] = Vs[kk][tx*4 + j];
            #pragma unroll
            for (int i = 0; i < 8; i++)
                #pragma unroll
                for (int j = 0; j < 4; j++) acc[i][j] += a[i] * bb[j];
        }
        __syncthreads();
    }

    #pragma unroll
    for (int i = 0; i < 8; i++) {
        int row = bm + ty*8 + i;
        #pragma unroll
        for (int j = 0; j < 4; j++) {
            Oz[(size_t)row * D_ + tx*4 + j] = acc[i][j];
        }
    }
}

// ============================================================
extern "C" void kernel_launch(void* const* d_in, const int* in_sizes, int n_in,
                              void* d_out, int out_size)
{
    const float* query = (const float*)d_in[0];
    const float* key   = (const float*)d_in[1];
    const float* value = (const float*)d_in[2];
    const float* W_q   = (const float*)d_in[3];
    const float* W_k   = (const float*)d_in[4];
    const float* W_v   = (const float*)d_in[5];
    const float* W_o   = (const float*)d_in[6];

    float* out   = (float*)d_out;                       // (B,S,D)
    float* attnw = out + (size_t)M_ * D_;               // (B,S,S)

    float *Q, *K, *V, *HO, *P;
    cudaGetSymbolAddress((void**)&Q,  g_Q);
    cudaGetSymbolAddress((void**)&K,  g_K);
    cudaGetSymbolAddress((void**)&V,  g_V);
    cudaGetSymbolAddress((void**)&HO, g_HO);
    cudaGetSymbolAddress((void**)&P,  g_P);

    dim3 blk(256);

    // 1) Projections: C[M,D] = X @ W^T
    {
        dim3 grid(D_/128, M_/128, 1);
        sgemm_nt_bat<<<grid, blk>>>(query, D_, 0, 0, W_q, D_, 0, 0,
                                    Q, D_, 0, 0, D_, 1.0f, 1);
        sgemm_nt_bat<<<grid, blk>>>(key,   D_, 0, 0, W_k, D_, 0, 0,
                                    K, D_, 0, 0, D_, 1.0f, 1);
        sgemm_nt_bat<<<grid, blk>>>(value, D_, 0, 0, W_v, D_, 0, 0,
                                    V, D_, 0, 0, D_, 1.0f, 1);
    }

    // 2) Scores: per (b,h): P = (Q_slice @ K_slice^T) / sqrt(dk)
    {
        dim3 grid(S_/128, S_/128, B_ * H_);
        sgemm_nt_bat<<<grid, blk>>>(
            Q, D_, (long)S_ * D_, DK_,
            K, D_, (long)S_ * D_, DK_,
            P, S_, (long)H_ * S_ * S_, (long)S_ * S_,
            DK_, 1.0f / 8.0f, H_);
    }

    // 3) Softmax rows + mean over heads (fused)
    softmax_mean<<<dim3(B_ * S_), blk>>>(P, attnw);

    // 4) head_out = attn @ V  -> (B,S,H,dk) laid out as [M, D]
    av_nn<<<dim3(S_/128, 1, B_ * H_), blk>>>(P, V, HO);

    // 5) out = head_out @ W_o^T
    {
        dim3 grid(D_/128, M_/128, 1);
        sgemm_nt_bat<<<grid, blk>>>(HO, D_, 0, 0, W_o, D_, 0, 0,
                                    out, D_, 0, 0, D_, 1.0f, 1);
    }
}

// round 4
// speedup vs baseline: 2.1714x; 2.1714x over previous
#include <cuda_runtime.h>
#include <cuda_bf16.h>
#include <math.h>
#include <stdint.h>

#define B_  2
#define S_  2048
#define D_  1024
#define H_  16
#define DK_ 64
#define M_  (B_*S_)   // 4096

// ---- scratch (static device globals; no allocation allowed) ----
__device__ float g_Q[(size_t)M_*D_];
__device__ float g_K[(size_t)M_*D_];
__device__ float g_V[(size_t)M_*D_];
__device__ float g_HO[(size_t)M_*D_];
__device__ float g_P[(size_t)B_*H_*S_*S_];   // 512 MB scores/probs

// ============================================================
// helpers
// ============================================================
__device__ __forceinline__ uint32_t smem_u32(const void* p) {
    return (uint32_t)__cvta_generic_to_shared(p);
}

__device__ __forceinline__ void ldsm_x4(uint32_t* r, uint32_t a) {
    asm volatile("ldmatrix.sync.aligned.m8n8.x4.shared.b16 {%0,%1,%2,%3}, [%4];"
                 : "=r"(r[0]), "=r"(r[1]), "=r"(r[2]), "=r"(r[3]) : "r"(a));
}
__device__ __forceinline__ void ldsm_x4_t(uint32_t* r, uint32_t a) {
    asm volatile("ldmatrix.sync.aligned.m8n8.x4.trans.shared.b16 {%0,%1,%2,%3}, [%4];"
                 : "=r"(r[0]), "=r"(r[1]), "=r"(r[2]), "=r"(r[3]) : "r"(a));
}
__device__ __forceinline__ void mma16816(float* c, const uint32_t* a,
                                         uint32_t b0, uint32_t b1) {
    asm volatile(
        "mma.sync.aligned.m16n8k16.row.col.f32.bf16.bf16.f32 "
        "{%0,%1,%2,%3},{%4,%5,%6,%7},{%8,%9},{%0,%1,%2,%3};"
        : "+f"(c[0]), "+f"(c[1]), "+f"(c[2]), "+f"(c[3])
        : "r"(a[0]), "r"(a[1]), "r"(a[2]), "r"(a[3]), "r"(b0), "r"(b1));
}

// split fp32 -> bf16 hi + bf16 lo (a ~= hi + lo, err ~2^-18)
__device__ __forceinline__ void split4(float4 v,
                                       __nv_bfloat162& h01, __nv_bfloat162& h23,
                                       __nv_bfloat162& l01, __nv_bfloat162& l23) {
    __nv_bfloat16 h0 = __float2bfloat16_rn(v.x);
    __nv_bfloat16 h1 = __float2bfloat16_rn(v.y);
    __nv_bfloat16 h2 = __float2bfloat16_rn(v.z);
    __nv_bfloat16 h3 = __float2bfloat16_rn(v.w);
    __nv_bfloat16 l0 = __float2bfloat16_rn(v.x - __bfloat162float(h0));
    __nv_bfloat16 l1 = __float2bfloat16_rn(v.y - __bfloat162float(h1));
    __nv_bfloat16 l2 = __float2bfloat16_rn(v.z - __bfloat162float(h2));
    __nv_bfloat16 l3 = __float2bfloat16_rn(v.w - __bfloat162float(h3));
    h01 = __halves2bfloat162(h0, h1); h23 = __halves2bfloat162(h2, h3);
    l01 = __halves2bfloat162(l0, l1); l23 = __halves2bfloat162(l2, l3);
}

// ============================================================
// Batched NT GEMM (tensor cores, bf16 split, fp32 accurate):
//   C[m,n] = alpha * sum_k A[m,k]*B[n,k]
// Block 128x128, BK=16, 256 threads (8 warps as 2x4), warp tile 64x32.
// Grid: (N/128, M/128, nz); z -> (zb=z/HB, zh=z%HB) stride offsets.
// ============================================================
#define APAD 24   // 16 data + 8 pad bf16 -> 48B row stride, LDSM conflict-free
__global__ __launch_bounds__(256, 1) void gemm_bf16s_nt(
    const float* __restrict__ A, int lda, long sAb, long sAh,
    const float* __restrict__ B, int ldb, long sBb, long sBh,
    float*       __restrict__ C, int ldc, long sCb, long sCh,
    int K, float alpha, int HB)
{
    int z  = blockIdx.z;
    int zb = z / HB, zh = z % HB;
    A += (size_t)zb * sAb + (size_t)zh * sAh;
    B += (size_t)zb * sBb + (size_t)zh * sBh;
    C += (size_t)zb * sCb + (size_t)zh * sCh;

    __shared__ __nv_bfloat16 Ah[128][APAD], Al[128][APAD];
    __shared__ __nv_bfloat16 Bh[128][APAD], Bl[128][APAD];

    const int tid  = threadIdx.x;
    const int lane = tid & 31;
    const int warp = tid >> 5;
    const int wm   = (warp >> 2) * 64;   // 0 or 64
    const int wn   = (warp & 3) * 32;    // 0..96
    const int bm   = blockIdx.y * 128;
    const int bn   = blockIdx.x * 128;

    const int lrow = tid >> 2;           // 0..63
    const int lc4  = tid & 3;            // float4 col in k

    float acc[4][4][4];
    #pragma unroll
    for (int i = 0; i < 4; i++)
        #pragma unroll
        for (int j = 0; j < 4; j++)
            #pragma unroll
            for (int c = 0; c < 4; c++) acc[i][j][c] = 0.f;

    // ldmatrix lane addresses (row within tile, k-submatrix select)
    const int lrow16 = lane & 15;
    const int ksub   = (lane >> 4) * 8;

    for (int k0 = 0; k0 < K; k0 += 16) {
        #pragma unroll
        for (int h = 0; h < 2; h++) {
            int row = lrow + h * 64;
            float4 va = *(const float4*)(A + (size_t)(bm + row) * lda + k0 + lc4 * 4);
            __nv_bfloat162 h01, h23, l01, l23;
            split4(va, h01, h23, l01, l23);
            *(__nv_bfloat162*)&Ah[row][lc4 * 4]     = h01;
            *(__nv_bfloat162*)&Ah[row][lc4 * 4 + 2] = h23;
            *(__nv_bfloat162*)&Al[row][lc4 * 4]     = l01;
            *(__nv_bfloat162*)&Al[row][lc4 * 4 + 2] = l23;

            float4 vb = *(const float4*)(B + (size_t)(bn + row) * ldb + k0 + lc4 * 4);
            split4(vb, h01, h23, l01, l23);
            *(__nv_bfloat162*)&Bh[row][lc4 * 4]     = h01;
            *(__nv_bfloat162*)&Bh[row][lc4 * 4 + 2] = h23;
            *(__nv_bfloat162*)&Bl[row][lc4 * 4]     = l01;
            *(__nv_bfloat162*)&Bl[row][lc4 * 4 + 2] = l23;
        }
        __syncthreads();

        uint32_t ah[4][4], al[4][4], bh[4][2], bl[4][2];
        #pragma unroll
        for (int mi = 0; mi < 4; mi++) {
            uint32_t ad = smem_u32(&Ah[wm + mi * 16 + lrow16][ksub]);
            ldsm_x4(ah[mi], ad);
            ad = smem_u32(&Al[wm + mi * 16 + lrow16][ksub]);
            ldsm_x4(al[mi], ad);
        }
        #pragma unroll
        for (int np = 0; np < 2; np++) {
            uint32_t r[4];
            uint32_t ad = smem_u32(&Bh[wn + np * 16 + lrow16][ksub]);
            ldsm_x4(r, ad);
            bh[2*np][0] = r[0]; bh[2*np+1][0] = r[1];
            bh[2*np][1] = r[2]; bh[2*np+1][1] = r[3];
            ad = smem_u32(&Bl[wn + np * 16 + lrow16][ksub]);
            ldsm_x4(r, ad);
            bl[2*np][0] = r[0]; bl[2*np+1][0] = r[1];
            bl[2*np][1] = r[2]; bl[2*np+1][1] = r[3];
        }

        #pragma unroll
        for (int mi = 0; mi < 4; mi++)
            #pragma unroll
            for (int ni = 0; ni < 4; ni++) {
                mma16816(acc[mi][ni], ah[mi], bh[ni][0], bh[ni][1]);
                mma16816(acc[mi][ni], ah[mi], bl[ni][0], bl[ni][1]);
                mma16816(acc[mi][ni], al[mi], bh[ni][0], bh[ni][1]);
            }
        __syncthreads();
    }

    const int g = lane >> 2, tg = lane & 3;
    #pragma unroll
    for (int mi = 0; mi < 4; mi++) {
        int r0 = bm + wm + mi * 16 + g;
        #pragma unroll
        for (int ni = 0; ni < 4; ni++) {
            int c0 = bn + wn + ni * 8 + tg * 2;
            float2 v0 = make_float2(alpha * acc[mi][ni][0], alpha * acc[mi][ni][1]);
            float2 v1 = make_float2(alpha * acc[mi][ni][2], alpha * acc[mi][ni][3]);
            *(float2*)&C[(size_t)r0 * ldc + c0]       = v0;
            *(float2*)&C[(size_t)(r0 + 8) * ldc + c0] = v1;
        }
    }
}

// ============================================================
// Fused softmax over last dim + mean over heads (unchanged from R1).
// ============================================================
__global__ __launch_bounds__(256) void softmax_mean(float* __restrict__ P,
                                                    float* __restrict__ W)
{
    const int b = blockIdx.x >> 11;
    const int s = blockIdx.x & (S_ - 1);
    const int tid = threadIdx.x;
    const int lane = tid & 31, wid = tid >> 5;

    __shared__ float red[8];

    float acc[8];
    #pragma unroll
    for (int i = 0; i < 8; i++) acc[i] = 0.f;

    const int c0 = tid * 4;
    const int c1 = 1024 + tid * 4;

    for (int h = 0; h < H_; h++) {
        float* row = P + ((size_t)(b * H_ + h) * S_ + s) * S_;
        float v[8];
        float4 f0 = *(const float4*)(row + c0);
        float4 f1 = *(const float4*)(row + c1);
        v[0]=f0.x; v[1]=f0.y; v[2]=f0.z; v[3]=f0.w;
        v[4]=f1.x; v[5]=f1.y; v[6]=f1.z; v[7]=f1.w;

        float m = v[0];
        #pragma unroll
        for (int i = 1; i < 8; i++) m = fmaxf(m, v[i]);
        #pragma unroll
        for (int o = 16; o > 0; o >>= 1) m = fmaxf(m, __shfl_xor_sync(0xffffffff, m, o));
        if (lane == 0) red[wid] = m;
        __syncthreads();
        if (wid == 0) {
            float t = red[lane & 7];
            #pragma unroll
            for (int o = 4; o > 0; o >>= 1) t = fmaxf(t, __shfl_xor_sync(0xffffffff, t, o));
            if (lane == 0) red[0] = t;
        }
        __syncthreads();
        m = red[0];
        __syncthreads();

        float sloc = 0.f;
        #pragma unroll
        for (int i = 0; i < 8; i++) { v[i] = __expf(v[i] - m); sloc += v[i]; }
        #pragma unroll
        for (int o = 16; o > 0; o >>= 1) sloc += __shfl_xor_sync(0xffffffff, sloc, o);
        if (lane == 0) red[wid] = sloc;
        __syncthreads();
        if (wid == 0) {
            float t = red[lane & 7];
            #pragma unroll
            for (int o = 4; o > 0; o >>= 1) t += __shfl_xor_sync(0xffffffff, t, o);
            if (lane == 0) red[0] = t;
        }
        __syncthreads();
        float inv = 1.0f / red[0];
        __syncthreads();

        #pragma unroll
        for (int i = 0; i < 8; i++) { v[i] *= inv; acc[i] += v[i] * (1.0f / H_); }
        *(float4*)(row + c0) = make_float4(v[0], v[1], v[2], v[3]);
        *(float4*)(row + c1) = make_float4(v[4], v[5], v[6], v[7]);
    }

    float* wrow = W + ((size_t)b * S_ + s) * S_;
    *(float4*)(wrow + c0) = make_float4(acc[0], acc[1], acc[2], acc[3]);
    *(float4*)(wrow + c1) = make_float4(acc[4], acc[5], acc[6], acc[7]);
}

// ============================================================
// attn @ V (tensor cores, NN): per (b,h): O[s,d] = sum_k P[s,k]*V[k,d]
// Block tile 128(M) x 64(N=dk), BK=16, 8 warps as 4x2, warp tile 32x32.
// B operand (V, k-major rows) fed via ldmatrix.trans.
// ============================================================
#define VPAD 72   // 64 data + 8 pad -> 144B row stride, conflict-free LDSM
__global__ __launch_bounds__(256, 1) void av_bf16s(const float* __restrict__ P,
                                                   const float* __restrict__ V,
                                                   float* __restrict__ O)
{
    const int z = blockIdx.z;
    const int b = z / H_, h = z % H_;
    const float* Pz = P + (size_t)z * S_ * S_;
    const float* Vz = V + (size_t)b * S_ * D_ + h * DK_;
    float*       Oz = O + (size_t)b * S_ * D_ + h * DK_;

    __shared__ __nv_bfloat16 Ph[128][APAD], Pl[128][APAD];
    __shared__ __nv_bfloat16 Vh[16][VPAD],  Vl[16][VPAD];

    const int tid  = threadIdx.x;
    const int lane = tid & 31;
    const int warp = tid >> 5;
    const int wm   = (warp >> 1) * 32;   // 0,32,64,96
    const int wn   = (warp & 1) * 32;    // 0,32
    const int bm   = blockIdx.x * 128;

    const int lrow = tid >> 2;           // 0..63 (P tile rows)
    const int lc4  = tid & 3;
    const int vrow = tid >> 4;           // 0..15 (V tile rows)
    const int vc4  = tid & 15;

    float acc[2][4][4];
    #pragma unroll
    for (int i = 0; i < 2; i++)
        #pragma unroll
        for (int j = 0; j < 4; j++)
            #pragma unroll
            for (int c = 0; c < 4; c++) acc[i][j][c] = 0.f;

    const int lrow16 = lane & 15;
    const int ksub   = (lane >> 4) * 8;

    for (int k0 = 0; k0 < S_; k0 += 16) {
        #pragma unroll
        for (int hh = 0; hh < 2; hh++) {
            int row = lrow + hh * 64;
            float4 va = *(const float4*)(Pz + (size_t)(bm + row) * S_ + k0 + lc4 * 4);
            __nv_bfloat162 h01, h23, l01, l23;
            split4(va, h01, h23, l01, l23);
            *(__nv_bfloat162*)&Ph[row][lc4 * 4]     = h01;
            *(__nv_bfloat162*)&Ph[row][lc4 * 4 + 2] = h23;
            *(__nv_bfloat162*)&Pl[row][lc4 * 4]     = l01;
            *(__nv_bfloat162*)&Pl[row][lc4 * 4 + 2] = l23;
        }
        {
            float4 vv = *(const float4*)(Vz + (size_t)(k0 + vrow) * D_ + vc4 * 4);
            __nv_bfloat162 h01, h23, l01, l23;
            split4(vv, h01, h23, l01, l23);
            *(__nv_bfloat162*)&Vh[vrow][vc4 * 4]     = h01;
            *(__nv_bfloat162*)&Vh[vrow][vc4 * 4 + 2] = h23;
            *(__nv_bfloat162*)&Vl[vrow][vc4 * 4]     = l01;
            *(__nv_bfloat162*)&Vl[vrow][vc4 * 4 + 2] = l23;
        }
        __syncthreads();

        uint32_t ah[2][4], al[2][4], bh[4][2], bl[4][2];
        #pragma unroll
        for (int mi = 0; mi < 2; mi++) {
            ldsm_x4(ah[mi], smem_u32(&Ph[wm + mi * 16 + lrow16][ksub]));
            ldsm_x4(al[mi], smem_u32(&Pl[wm + mi * 16 + lrow16][ksub]));
        }
        #pragma unroll
        for (int np = 0; np < 2; np++) {
            uint32_t r[4];
            ldsm_x4_t(r, smem_u32(&Vh[lrow16][wn + np * 16 + ksub]));
            bh[2*np][0] = r[0]; bh[2*np][1] = r[1];
            bh[2*np+1][0] = r[2]; bh[2*np+1][1] = r[3];
            ldsm_x4_t(r, smem_u32(&Vl[lrow16][wn + np * 16 + ksub]));
            bl[2*np][0] = r[0]; bl[2*np][1] = r[1];
            bl[2*np+1][0] = r[2]; bl[2*np+1][1] = r[3];
        }

        #pragma unroll
        for (int mi = 0; mi < 2; mi++)
            #pragma unroll
            for (int ni = 0; ni < 4; ni++) {
                mma16816(acc[mi][ni], ah[mi], bh[ni][0], bh[ni][1]);
                mma16816(acc[mi][ni], ah[mi], bl[ni][0], bl[ni][1]);
                mma16816(acc[mi][ni], al[mi], bh[ni][0], bh[ni][1]);
            }
        __syncthreads();
    }

    const int g = lane >> 2, tg = lane & 3;
    #pragma unroll
    for (int mi = 0; mi < 2; mi++) {
        int r0 = bm + wm + mi * 16 + g;
        #pragma unroll
        for (int ni = 0; ni < 4; ni++) {
            int c0 = wn + ni * 8 + tg * 2;
            *(float2*)&Oz[(size_t)r0 * D_ + c0] =
                make_float2(acc[mi][ni][0], acc[mi][ni][1]);
            *(float2*)&Oz[(size_t)(r0 + 8) * D_ + c0] =
                make_float2(acc[mi][ni][2], acc[mi][ni][3]);
        }
    }
}

// ============================================================
extern "C" void kernel_launch(void* const* d_in, const int* in_sizes, int n_in,
                              void* d_out, int out_size)
{
    const float* query = (const float*)d_in[0];
    const float* key   = (const float*)d_in[1];
    const float* value = (const float*)d_in[2];
    const float* W_q   = (const float*)d_in[3];
    const float* W_k   = (const float*)d_in[4];
    const float* W_v   = (const float*)d_in[5];
    const float* W_o   = (const float*)d_in[6];

    float* out   = (float*)d_out;               // (B,S,D)
    float* attnw = out + (size_t)M_ * D_;       // (B,S,S)

    float *Q, *K, *V, *HO, *P;
    cudaGetSymbolAddress((void**)&Q,  g_Q);
    cudaGetSymbolAddress((void**)&K,  g_K);
    cudaGetSymbolAddress((void**)&V,  g_V);
    cudaGetSymbolAddress((void**)&HO, g_HO);
    cudaGetSymbolAddress((void**)&P,  g_P);

    dim3 blk(256);

    // 1) Projections: C[M,D] = X @ W^T
    {
        dim3 grid(D_/128, M_/128, 1);
        gemm_bf16s_nt<<<grid, blk>>>(query, D_, 0, 0, W_q, D_, 0, 0,
                                     Q, D_, 0, 0, D_, 1.0f, 1);
        gemm_bf16s_nt<<<grid, blk>>>(key,   D_, 0, 0, W_k, D_, 0, 0,
                                     K, D_, 0, 0, D_, 1.0f, 1);
        gemm_bf16s_nt<<<grid, blk>>>(value, D_, 0, 0, W_v, D_, 0, 0,
                                     V, D_, 0, 0, D_, 1.0f, 1);
    }

    // 2) Scores: per (b,h): P = (Q_slice @ K_slice^T) / 8
    {
        dim3 grid(S_/128, S_/128, B_ * H_);
        gemm_bf16s_nt<<<grid, blk>>>(
            Q, D_, (long)S_ * D_, DK_,
            K, D_, (long)S_ * D_, DK_,
            P, S_, (long)H_ * S_ * S_, (long)S_ * S_,
            DK_, 0.125f, H_);
    }

    // 3) Softmax rows + mean over heads
    softmax_mean<<<dim3(B_ * S_), blk>>>(P, attnw);

    // 4) head_out = attn @ V
    av_bf16s<<<dim3(S_/128, 1, B_ * H_), blk>>>(P, V, HO);

    // 5) out = head_out @ W_o^T
    {
        dim3 grid(D_/128, M_/128, 1);
        gemm_bf16s_nt<<<grid, blk>>>(HO, D_, 0, 0, W_o, D_, 0, 0,
                                     out, D_, 0, 0, D_, 1.0f, 1);
    }
}